// round 4
// baseline (speedup 1.0000x reference)
#include <cuda_runtime.h>
#include <cuda_bf16.h>
#include <cstdint>

// Problem constants
#define NWIN  4096
#define NTOK  64
#define DIM   192
#define HEADS 6
#define QK_SCALE 0.17677669529663687f   // 32^-0.5

#define NTHREADS 512

// smem layout
#define CPAD  196   // fp32 row stride for Q/K/V
#define XPADW 36    // uint32 row stride for packed-bf16x2 A buffers (bank = 4g+t, conflict-free)
#define OFF_XB 0                           // [64][36] uint32  A big  (bf16x2 pairs)
#define OFF_XS (OFF_XB + NTOK*XPADW)       // [64][36] uint32  A small
#define OFF_SQ (OFF_XS + NTOK*XPADW)       // [64][196] fp32 Q (scaled) -> later O in-place
#define OFF_SK (OFF_SQ + NTOK*CPAD)
#define OFF_SV (OFF_SK + NTOK*CPAD)
#define SMEM_WORDS (OFF_SV + NTOK*CPAD)    // 42240 words = 168960 bytes

// Packed weights: [ks16 0..11][ntile][lane] = {big_b0, big_b1, sml_b0, sml_b1} (bf16x2 each)
#define NQ_FRAG (12 * 72 * 32)
#define NP_FRAG (12 * 24 * 32)
#define NB_ELEM (HEADS * NTOK * NTOK)
__device__ uint4 g_wqkv[NQ_FRAG];
__device__ uint4 g_wproj[NP_FRAG];
__device__ float g_bias[NB_ELEM];

__device__ __forceinline__ uint32_t pack2(__nv_bfloat162 p) {
    return *reinterpret_cast<uint32_t*>(&p);   // .x in low 16 bits (lower k)
}

// big/small bf16 pair split of two fp32 values (v0 = lower-k element)
__device__ __forceinline__ void split2(float v0, float v1, uint32_t& big, uint32_t& sml) {
    __nv_bfloat162 b = __floats2bfloat162_rn(v0, v1);
    float r0 = v0 - __bfloat162float(b.x);
    float r1 = v1 - __bfloat162float(b.y);
    __nv_bfloat162 s = __floats2bfloat162_rn(r0, r1);
    big = pack2(b); sml = pack2(s);
}

#define MMA_BF16(C, A0, A1, A2, A3, B0, B1)                                          \
    asm("mma.sync.aligned.m16n8k16.row.col.f32.bf16.bf16.f32 "                       \
        "{%0,%1,%2,%3},{%4,%5,%6,%7},{%8,%9},{%0,%1,%2,%3};"                         \
        : "+f"((C)[0]), "+f"((C)[1]), "+f"((C)[2]), "+f"((C)[3])                     \
        : "r"(A0), "r"(A1), "r"(A2), "r"(A3), "r"(B0), "r"(B1))

// One prep kernel: pack both weight matrices into B-fragment order + expand bias.
__global__ void prep_kernel(const float* __restrict__ qkv_w,
                            const float* __restrict__ proj_w,
                            const float* __restrict__ bias_table,
                            const int* __restrict__ rel_index) {
    int idx = blockIdx.x * blockDim.x + threadIdx.x;
    if (idx < NQ_FRAG) {
        int lane = idx & 31, nt = (idx >> 5) % 72, ks = idx / (72 * 32);
        int g = lane >> 2, t = lane & 3;
        int n = nt * 8 + g, k0 = ks * 16 + 2 * t;
        uint32_t bb0, bs0, bb1, bs1;
        split2(qkv_w[n * DIM + k0],     qkv_w[n * DIM + k0 + 1], bb0, bs0);
        split2(qkv_w[n * DIM + k0 + 8], qkv_w[n * DIM + k0 + 9], bb1, bs1);
        g_wqkv[idx] = make_uint4(bb0, bb1, bs0, bs1);
    } else if (idx < NQ_FRAG + NP_FRAG) {
        int j = idx - NQ_FRAG;
        int lane = j & 31, nt = (j >> 5) % 24, ks = j / (24 * 32);
        int g = lane >> 2, t = lane & 3;
        int n = nt * 8 + g, k0 = ks * 16 + 2 * t;
        uint32_t bb0, bs0, bb1, bs1;
        split2(proj_w[n * DIM + k0],     proj_w[n * DIM + k0 + 1], bb0, bs0);
        split2(proj_w[n * DIM + k0 + 8], proj_w[n * DIM + k0 + 9], bb1, bs1);
        g_wproj[j] = make_uint4(bb0, bb1, bs0, bs1);
    } else if (idx < NQ_FRAG + NP_FRAG + NB_ELEM) {
        int e = idx - NQ_FRAG - NP_FRAG;
        int h  = e / (NTOK * NTOK);
        int ij = e % (NTOK * NTOK);
        g_bias[e] = bias_table[rel_index[ij] * HEADS + h];
    }
}

// Stage a [64 x 64] fp32 chunk into packed big/small bf16x2 smem (512 threads -> 2 iters).
#define STAGE_CHUNK(SRC_BASE, SRC_STRIDE, COL0)                                      \
    do {                                                                             \
        _Pragma("unroll")                                                            \
        for (int it = 0; it < 2; ++it) {                                             \
            int idx = tid + NTHREADS * it;                                           \
            int r  = idx >> 4;                                                       \
            int c4 = (idx & 15) * 4;                                                 \
            float4 v = *reinterpret_cast<const float4*>((SRC_BASE) + r * (SRC_STRIDE) + (COL0) + c4); \
            uint32_t b0, s0, b1, s1;                                                 \
            split2(v.x, v.y, b0, s0);                                                \
            split2(v.z, v.w, b1, s1);                                                \
            int w = r * XPADW + (c4 >> 1);                                           \
            XB[w] = b0; XB[w + 1] = b1;                                              \
            XS[w] = s0; XS[w + 1] = s1;                                              \
        }                                                                            \
    } while (0)

__global__ __launch_bounds__(NTHREADS, 1)
void msa_fused_kernel(const float* __restrict__ x,
                      const float* __restrict__ qkv_b,
                      const float* __restrict__ proj_b,
                      float* __restrict__ out)
{
    extern __shared__ uint32_t smu[];
    uint32_t* XB = smu + OFF_XB;
    uint32_t* XS = smu + OFF_XS;
    float* SQ = reinterpret_cast<float*>(smu + OFF_SQ);   // Q, then O in-place
    float* SK = reinterpret_cast<float*>(smu + OFF_SK);
    float* SV = reinterpret_cast<float*>(smu + OFF_SV);

    const int tid  = threadIdx.x;
    const int lane = tid & 31;
    const int warp = tid >> 5;     // 0..15
    const int wc   = warp & 7;     // column group (72 cols)
    const int mh   = warp >> 3;    // m-half (rows mh*32 .. mh*32+31)
    const int g    = lane >> 2;
    const int t    = lane & 3;
    const int b    = blockIdx.x;
    const float* xb = x + (size_t)b * (NTOK * DIM);
    float* ob       = out + (size_t)b * (NTOK * DIM);

    // ================= Phase 1: QKV GEMM (3x bf16 mma) =================
    {
        float c[2][9][4];
        #pragma unroll
        for (int mt = 0; mt < 2; ++mt)
            #pragma unroll
            for (int nt = 0; nt < 9; ++nt)
                #pragma unroll
                for (int i = 0; i < 4; ++i) c[mt][nt][i] = 0.f;

        for (int kb = 0; kb < 3; ++kb) {
            __syncthreads();
            STAGE_CHUNK(xb, DIM, kb * 64);
            __syncthreads();
            #pragma unroll
            for (int ksl = 0; ksl < 4; ++ksl) {
                uint32_t ab[2][4], as[2][4];
                const int wb = ksl * 8 + t;
                #pragma unroll
                for (int mt = 0; mt < 2; ++mt) {
                    int r0 = (mh * 32 + mt * 16 + g) * XPADW, r1 = r0 + 8 * XPADW;
                    ab[mt][0] = XB[r0 + wb];     ab[mt][1] = XB[r1 + wb];
                    ab[mt][2] = XB[r0 + wb + 4]; ab[mt][3] = XB[r1 + wb + 4];
                    as[mt][0] = XS[r0 + wb];     as[mt][1] = XS[r1 + wb];
                    as[mt][2] = XS[r0 + wb + 4]; as[mt][3] = XS[r1 + wb + 4];
                }
                const int ksg = kb * 4 + ksl;
                #pragma unroll
                for (int nt = 0; nt < 9; ++nt) {
                    uint4 B4 = g_wqkv[(ksg * 72 + wc * 9 + nt) * 32 + lane];
                    #pragma unroll
                    for (int mt = 0; mt < 2; ++mt) {
                        MMA_BF16(c[mt][nt], ab[mt][0], ab[mt][1], ab[mt][2], ab[mt][3], B4.x, B4.y);
                        MMA_BF16(c[mt][nt], ab[mt][0], ab[mt][1], ab[mt][2], ab[mt][3], B4.z, B4.w);
                        MMA_BF16(c[mt][nt], as[mt][0], as[mt][1], as[mt][2], as[mt][3], B4.x, B4.y);
                    }
                }
            }
        }
        // Epilogue: + bias, scatter to SQ (scaled) / SK / SV
        #pragma unroll
        for (int nt = 0; nt < 9; ++nt) {
            int colbase = wc * 72 + nt * 8 + 2 * t;
            #pragma unroll
            for (int ii = 0; ii < 2; ++ii) {
                int gcol = colbase + ii;
                float bias = qkv_b[gcol];
                #pragma unroll
                for (int mt = 0; mt < 2; ++mt)
                    #pragma unroll
                    for (int rr = 0; rr < 2; ++rr) {
                        float v = c[mt][nt][rr * 2 + ii] + bias;
                        int row = mh * 32 + mt * 16 + g + 8 * rr;
                        if (gcol < DIM)            SQ[row * CPAD + gcol]            = v * QK_SCALE;
                        else if (gcol < 2 * DIM)   SK[row * CPAD + gcol - DIM]      = v;
                        else                       SV[row * CPAD + gcol - 2 * DIM]  = v;
                    }
            }
        }
    }
    __syncthreads();

    // ================= Phase 2: attention (FFMA), 8 threads/row, O in-place over Q ====
    {
        const int r  = tid >> 3;
        const int qq = tid & 7;
        for (int h = 0; h < HEADS; ++h) {
            float qreg[32];
            #pragma unroll
            for (int dc = 0; dc < 8; ++dc) {
                float4 v = *reinterpret_cast<const float4*>(&SQ[r * CPAD + h * 32 + dc * 4]);
                qreg[dc * 4 + 0] = v.x; qreg[dc * 4 + 1] = v.y;
                qreg[dc * 4 + 2] = v.z; qreg[dc * 4 + 3] = v.w;
            }
            const float* gb = g_bias + h * (NTOK * NTOK) + r * NTOK;
            float s[8];
            #pragma unroll
            for (int jj = 0; jj < 8; ++jj) {
                int j = jj * 8 + qq;
                float a = 0.f;
                #pragma unroll
                for (int dc = 0; dc < 8; ++dc) {
                    float4 kv = *reinterpret_cast<const float4*>(&SK[j * CPAD + h * 32 + dc * 4]);
                    a += qreg[dc * 4 + 0] * kv.x + qreg[dc * 4 + 1] * kv.y
                       + qreg[dc * 4 + 2] * kv.z + qreg[dc * 4 + 3] * kv.w;
                }
                s[jj] = a + gb[j];
            }
            float m = s[0];
            #pragma unroll
            for (int jj = 1; jj < 8; ++jj) m = fmaxf(m, s[jj]);
            m = fmaxf(m, __shfl_xor_sync(0xffffffffu, m, 1));
            m = fmaxf(m, __shfl_xor_sync(0xffffffffu, m, 2));
            m = fmaxf(m, __shfl_xor_sync(0xffffffffu, m, 4));
            float l = 0.f;
            #pragma unroll
            for (int jj = 0; jj < 8; ++jj) { s[jj] = __expf(s[jj] - m); l += s[jj]; }
            l += __shfl_xor_sync(0xffffffffu, l, 1);
            l += __shfl_xor_sync(0xffffffffu, l, 2);
            l += __shfl_xor_sync(0xffffffffu, l, 4);
            float o[32];
            #pragma unroll
            for (int d = 0; d < 32; ++d) o[d] = 0.f;
            #pragma unroll
            for (int jj = 0; jj < 8; ++jj) {
                int j = jj * 8 + qq;
                float p = s[jj];
                #pragma unroll
                for (int dc = 0; dc < 8; ++dc) {
                    float4 vv = *reinterpret_cast<const float4*>(&SV[j * CPAD + h * 32 + dc * 4]);
                    o[dc * 4 + 0] += p * vv.x; o[dc * 4 + 1] += p * vv.y;
                    o[dc * 4 + 2] += p * vv.z; o[dc * 4 + 3] += p * vv.w;
                }
            }
            #pragma unroll
            for (int d = 0; d < 32; ++d) {
                o[d] += __shfl_xor_sync(0xffffffffu, o[d], 1);
                o[d] += __shfl_xor_sync(0xffffffffu, o[d], 2);
                o[d] += __shfl_xor_sync(0xffffffffu, o[d], 4);
            }
            float linv = 1.f / l;
            #pragma unroll
            for (int u = 0; u < 4; ++u) {
                int d = u * 8 + qq;
                SQ[r * CPAD + h * 32 + d] = o[d] * linv;
            }
        }
    }
    __syncthreads();

    // ================= Phase 3: proj GEMM (3x bf16 mma), A = O (in SQ) =================
    {
        float c[2][3][4];
        #pragma unroll
        for (int mt = 0; mt < 2; ++mt)
            #pragma unroll
            for (int nt = 0; nt < 3; ++nt)
                #pragma unroll
                for (int i = 0; i < 4; ++i) c[mt][nt][i] = 0.f;

        for (int kb = 0; kb < 3; ++kb) {
            __syncthreads();
            STAGE_CHUNK(SQ, CPAD, kb * 64);
            __syncthreads();
            #pragma unroll
            for (int ksl = 0; ksl < 4; ++ksl) {
                uint32_t ab[2][4], as[2][4];
                const int wb = ksl * 8 + t;
                #pragma unroll
                for (int mt = 0; mt < 2; ++mt) {
                    int r0 = (mh * 32 + mt * 16 + g) * XPADW, r1 = r0 + 8 * XPADW;
                    ab[mt][0] = XB[r0 + wb];     ab[mt][1] = XB[r1 + wb];
                    ab[mt][2] = XB[r0 + wb + 4]; ab[mt][3] = XB[r1 + wb + 4];
                    as[mt][0] = XS[r0 + wb];     as[mt][1] = XS[r1 + wb];
                    as[mt][2] = XS[r0 + wb + 4]; as[mt][3] = XS[r1 + wb + 4];
                }
                const int ksg = kb * 4 + ksl;
                #pragma unroll
                for (int nt = 0; nt < 3; ++nt) {
                    uint4 B4 = g_wproj[(ksg * 24 + wc * 3 + nt) * 32 + lane];
                    #pragma unroll
                    for (int mt = 0; mt < 2; ++mt) {
                        MMA_BF16(c[mt][nt], ab[mt][0], ab[mt][1], ab[mt][2], ab[mt][3], B4.x, B4.y);
                        MMA_BF16(c[mt][nt], ab[mt][0], ab[mt][1], ab[mt][2], ab[mt][3], B4.z, B4.w);
                        MMA_BF16(c[mt][nt], as[mt][0], as[mt][1], as[mt][2], as[mt][3], B4.x, B4.y);
                    }
                }
            }
        }
        // Epilogue: + bias, write to gmem (float2 pairs)
        #pragma unroll
        for (int nt = 0; nt < 3; ++nt) {
            int colbase = wc * 24 + nt * 8 + 2 * t;
            float b0 = proj_b[colbase], b1 = proj_b[colbase + 1];
            #pragma unroll
            for (int mt = 0; mt < 2; ++mt)
                #pragma unroll
                for (int rr = 0; rr < 2; ++rr) {
                    int row = mh * 32 + mt * 16 + g + 8 * rr;
                    float2 v;
                    v.x = c[mt][nt][rr * 2 + 0] + b0;
                    v.y = c[mt][nt][rr * 2 + 1] + b1;
                    *reinterpret_cast<float2*>(ob + row * DIM + colbase) = v;
                }
        }
    }
}

extern "C" void kernel_launch(void* const* d_in, const int* in_sizes, int n_in,
                              void* d_out, int out_size) {
    const float* x          = (const float*)d_in[0];
    const float* qkv_w      = (const float*)d_in[1];
    const float* qkv_b      = (const float*)d_in[2];
    const float* proj_w     = (const float*)d_in[3];
    const float* proj_b     = (const float*)d_in[4];
    const float* bias_table = (const float*)d_in[5];
    const int*   rel_index  = (const int*)d_in[6];
    float* out = (float*)d_out;

    cudaFuncSetAttribute(msa_fused_kernel, cudaFuncAttributeMaxDynamicSharedMemorySize,
                         SMEM_WORDS * (int)sizeof(uint32_t));

    int prep_n = NQ_FRAG + NP_FRAG + NB_ELEM;
    prep_kernel<<<(prep_n + 255) / 256, 256>>>(qkv_w, proj_w, bias_table, rel_index);
    msa_fused_kernel<<<NWIN, NTHREADS, SMEM_WORDS * sizeof(uint32_t)>>>(x, qkv_b, proj_b, out);
}

// round 5
// speedup vs baseline: 3.3640x; 3.3640x over previous
#include <cuda_runtime.h>
#include <cuda_bf16.h>
#include <cstdint>

// Problem constants
#define NWIN  4096
#define NTOK  64
#define DIM   192
#define HEADS 6
#define QK_SCALE 0.17677669529663687f   // 32^-0.5

#define NTHREADS 512

// smem (uint32 words). APAD/VPAD mod 32 == 4 -> fragment banks 4g+t, conflict-free.
#define APAD 100   // 96 packed words (192 bf16-pairs) + 4 pad
#define VPAD 36    // 32 packed words (64 j-pairs) + 4 pad
#define OFF_AB  0                        // [64][100] x big, later O big
#define OFF_AS  (OFF_AB  + 64*APAD)      // [64][100] x small, later O small
#define OFF_QB  (OFF_AS  + 64*APAD)
#define OFF_QS  (OFF_QB  + 64*APAD)
#define OFF_KB  (OFF_QS  + 64*APAD)
#define OFF_KS  (OFF_KB  + 64*APAD)
#define OFF_VTB (OFF_KS  + 64*APAD)      // [192][36] V^T big (pairs along j)
#define OFF_VTS (OFF_VTB + 192*VPAD)
#define SMEM_WORDS (OFF_VTS + 192*VPAD)  // 52224 words = 208896 B

// Device-global prepacked data
#define NQ_FRAG (12 * 72 * 32)
#define NP_FRAG (12 * 24 * 32)
#define NBF     (HEADS * 4 * 8 * 32)     // bias in C-fragment layout
__device__ uint4  g_wqkv[NQ_FRAG];   // {big_b0, big_b1, sml_b0, sml_b1}
__device__ uint4  g_wproj[NP_FRAG];
__device__ float4 g_biasf[NBF];      // {c0,c1,c2,c3} per lane

__device__ __forceinline__ uint32_t pack2(__nv_bfloat162 p) {
    return *reinterpret_cast<uint32_t*>(&p);
}
__device__ __forceinline__ void split2(float v0, float v1, uint32_t& big, uint32_t& sml) {
    __nv_bfloat162 b = __floats2bfloat162_rn(v0, v1);
    float r0 = v0 - __bfloat162float(b.x);
    float r1 = v1 - __bfloat162float(b.y);
    __nv_bfloat162 s = __floats2bfloat162_rn(r0, r1);
    big = pack2(b); sml = pack2(s);
}

#define MMA_BF16(C, A0, A1, A2, A3, B0, B1)                                          \
    asm("mma.sync.aligned.m16n8k16.row.col.f32.bf16.bf16.f32 "                       \
        "{%0,%1,%2,%3},{%4,%5,%6,%7},{%8,%9},{%0,%1,%2,%3};"                         \
        : "+f"((C)[0]), "+f"((C)[1]), "+f"((C)[2]), "+f"((C)[3])                     \
        : "r"(A0), "r"(A1), "r"(A2), "r"(A3), "r"(B0), "r"(B1))

// Prep: pack weights into B-fragment order; expand bias into C-fragment layout.
__global__ void prep_kernel(const float* __restrict__ qkv_w,
                            const float* __restrict__ proj_w,
                            const float* __restrict__ bias_table,
                            const int* __restrict__ rel_index) {
    int idx = blockIdx.x * blockDim.x + threadIdx.x;
    if (idx < NQ_FRAG) {
        int lane = idx & 31, nt = (idx >> 5) % 72, ks = idx / (72 * 32);
        int g = lane >> 2, t = lane & 3;
        int n = nt * 8 + g, k0 = ks * 16 + 2 * t;
        uint32_t bb0, bs0, bb1, bs1;
        split2(qkv_w[n * DIM + k0],     qkv_w[n * DIM + k0 + 1], bb0, bs0);
        split2(qkv_w[n * DIM + k0 + 8], qkv_w[n * DIM + k0 + 9], bb1, bs1);
        g_wqkv[idx] = make_uint4(bb0, bb1, bs0, bs1);
    } else if (idx < NQ_FRAG + NP_FRAG) {
        int j = idx - NQ_FRAG;
        int lane = j & 31, nt = (j >> 5) % 24, ks = j / (24 * 32);
        int g = lane >> 2, t = lane & 3;
        int n = nt * 8 + g, k0 = ks * 16 + 2 * t;
        uint32_t bb0, bs0, bb1, bs1;
        split2(proj_w[n * DIM + k0],     proj_w[n * DIM + k0 + 1], bb0, bs0);
        split2(proj_w[n * DIM + k0 + 8], proj_w[n * DIM + k0 + 9], bb1, bs1);
        g_wproj[j] = make_uint4(bb0, bb1, bs0, bs1);
    } else if (idx < NQ_FRAG + NP_FRAG + NBF) {
        int e = idx - NQ_FRAG - NP_FRAG;
        int lane = e & 31, nt = (e >> 5) & 7, mt = (e >> 8) & 3, h = e >> 10;
        int g = lane >> 2, t = lane & 3;
        int r0 = mt * 16 + g, c0 = nt * 8 + 2 * t;
        float4 v;
        v.x = bias_table[rel_index[r0 * NTOK + c0]           * HEADS + h];
        v.y = bias_table[rel_index[r0 * NTOK + c0 + 1]       * HEADS + h];
        v.z = bias_table[rel_index[(r0 + 8) * NTOK + c0]     * HEADS + h];
        v.w = bias_table[rel_index[(r0 + 8) * NTOK + c0 + 1] * HEADS + h];
        g_biasf[e] = v;
    }
}

__global__ __launch_bounds__(NTHREADS, 1)
void msa_fused_kernel(const float* __restrict__ x,
                      const float* __restrict__ qkv_b,
                      const float* __restrict__ proj_b,
                      float* __restrict__ out)
{
    extern __shared__ uint32_t smu[];
    uint32_t* AB  = smu + OFF_AB;   // x big -> later O big
    uint32_t* AS  = smu + OFF_AS;
    uint32_t* QB  = smu + OFF_QB;
    uint32_t* QS  = smu + OFF_QS;
    uint32_t* KB  = smu + OFF_KB;
    uint32_t* KS  = smu + OFF_KS;
    uint32_t* VTB = smu + OFF_VTB;
    uint32_t* VTS = smu + OFF_VTS;
    __nv_bfloat16* VTB16 = reinterpret_cast<__nv_bfloat16*>(VTB);
    __nv_bfloat16* VTS16 = reinterpret_cast<__nv_bfloat16*>(VTS);

    const int tid  = threadIdx.x;
    const int lane = tid & 31;
    const int warp = tid >> 5;     // 0..15
    const int wc   = warp & 7;     // column group (72 cols)
    const int mh   = warp >> 3;    // m-half
    const int g    = lane >> 2;
    const int t    = lane & 3;
    const int b    = blockIdx.x;
    const float* xb = x + (size_t)b * (NTOK * DIM);
    float* ob       = out + (size_t)b * (NTOK * DIM);

    // ---- Stage x once as big/small bf16x2 (fragment-load layout) ----
    #pragma unroll
    for (int it = 0; it < 6; ++it) {
        int idx = tid + NTHREADS * it;     // 0..3071
        int r  = idx / 48;                 // 48 float4 per row
        int c4 = (idx % 48) * 4;
        float4 v = *reinterpret_cast<const float4*>(xb + r * DIM + c4);
        uint32_t b0, s0, b1, s1;
        split2(v.x, v.y, b0, s0);
        split2(v.z, v.w, b1, s1);
        int w = r * APAD + (c4 >> 1);
        AB[w] = b0; AB[w + 1] = b1;
        AS[w] = s0; AS[w + 1] = s1;
    }
    __syncthreads();

    // ================= Phase 1: QKV GEMM (3x bf16 mma) =================
    {
        float c[2][9][4];
        #pragma unroll
        for (int mt = 0; mt < 2; ++mt)
            #pragma unroll
            for (int nt = 0; nt < 9; ++nt)
                #pragma unroll
                for (int i = 0; i < 4; ++i) c[mt][nt][i] = 0.f;

        for (int ksg = 0; ksg < 12; ++ksg) {
            uint32_t ab[2][4], as[2][4];
            const int wb = ksg * 8 + t;
            #pragma unroll
            for (int mt = 0; mt < 2; ++mt) {
                int r0 = (mh * 32 + mt * 16 + g) * APAD, r1 = r0 + 8 * APAD;
                ab[mt][0] = AB[r0 + wb];     ab[mt][1] = AB[r1 + wb];
                ab[mt][2] = AB[r0 + wb + 4]; ab[mt][3] = AB[r1 + wb + 4];
                as[mt][0] = AS[r0 + wb];     as[mt][1] = AS[r1 + wb];
                as[mt][2] = AS[r0 + wb + 4]; as[mt][3] = AS[r1 + wb + 4];
            }
            #pragma unroll
            for (int nt = 0; nt < 9; ++nt) {
                uint4 B4 = g_wqkv[(ksg * 72 + wc * 9 + nt) * 32 + lane];
                #pragma unroll
                for (int mt = 0; mt < 2; ++mt) {
                    MMA_BF16(c[mt][nt], ab[mt][0], ab[mt][1], ab[mt][2], ab[mt][3], B4.x, B4.y);
                    MMA_BF16(c[mt][nt], ab[mt][0], ab[mt][1], ab[mt][2], ab[mt][3], B4.z, B4.w);
                    MMA_BF16(c[mt][nt], as[mt][0], as[mt][1], as[mt][2], as[mt][3], B4.x, B4.y);
                }
            }
        }
        __syncthreads();   // x fragment reads done; AB/AS will be reused for O
        // Epilogue: + bias, write packed big/small bf16 Q/K and transposed V
        #pragma unroll
        for (int nt = 0; nt < 9; ++nt) {
            int colbase = wc * 72 + nt * 8 + 2 * t;   // even
            float bias0 = qkv_b[colbase], bias1 = qkv_b[colbase + 1];
            #pragma unroll
            for (int mt = 0; mt < 2; ++mt)
                #pragma unroll
                for (int rr = 0; rr < 2; ++rr) {
                    int row = mh * 32 + mt * 16 + g + 8 * rr;
                    float v0 = c[mt][nt][rr * 2 + 0] + bias0;
                    float v1 = c[mt][nt][rr * 2 + 1] + bias1;
                    if (colbase < DIM) {
                        uint32_t bb, ss;
                        split2(v0 * QK_SCALE, v1 * QK_SCALE, bb, ss);
                        int w = row * APAD + (colbase >> 1);
                        QB[w] = bb; QS[w] = ss;
                    } else if (colbase < 2 * DIM) {
                        uint32_t bb, ss;
                        split2(v0, v1, bb, ss);
                        int w = row * APAD + ((colbase - DIM) >> 1);
                        KB[w] = bb; KS[w] = ss;
                    } else {
                        int d0 = colbase - 2 * DIM;
                        __nv_bfloat16 b0 = __float2bfloat16(v0);
                        __nv_bfloat16 b1 = __float2bfloat16(v1);
                        VTB16[d0 * (2 * VPAD) + row]       = b0;
                        VTB16[(d0 + 1) * (2 * VPAD) + row] = b1;
                        VTS16[d0 * (2 * VPAD) + row]       = __float2bfloat16(v0 - __bfloat162float(b0));
                        VTS16[(d0 + 1) * (2 * VPAD) + row] = __float2bfloat16(v1 - __bfloat162float(b1));
                    }
                }
        }
    }
    __syncthreads();

    // ================= Phase 2: attention, fully tensor-core, register softmax =========
    // Job = (h, mt): 16 query rows of head h. 24 jobs over 16 warps.
    for (int job = warp; job < HEADS * 4; job += 16) {
        int h = job >> 2, mt = job & 3;
        int r0 = mt * 16 + g;

        // Q fragments (k=32 -> 2 chunks)
        uint32_t qb[2][4], qs[2][4];
        #pragma unroll
        for (int kc = 0; kc < 2; ++kc) {
            int w0 = r0 * APAD + h * 16 + kc * 8 + t;
            int w1 = w0 + 8 * APAD;
            qb[kc][0] = QB[w0]; qb[kc][1] = QB[w1];
            qb[kc][2] = QB[w0 + 4]; qb[kc][3] = QB[w1 + 4];
            qs[kc][0] = QS[w0]; qs[kc][1] = QS[w1];
            qs[kc][2] = QS[w0 + 4]; qs[kc][3] = QS[w1 + 4];
        }
        // S = bias + Q K^T (3-split)
        float s[8][4];
        #pragma unroll
        for (int nt = 0; nt < 8; ++nt) {
            float4 bf = g_biasf[((h * 4 + mt) * 8 + nt) * 32 + lane];
            s[nt][0] = bf.x; s[nt][1] = bf.y; s[nt][2] = bf.z; s[nt][3] = bf.w;
            int jr = (nt * 8 + g) * APAD + h * 16;
            #pragma unroll
            for (int kc = 0; kc < 2; ++kc) {
                int w0 = jr + kc * 8 + t;
                uint32_t kb0 = KB[w0], kb1 = KB[w0 + 4];
                uint32_t ks0 = KS[w0], ks1 = KS[w0 + 4];
                MMA_BF16(s[nt], qb[kc][0], qb[kc][1], qb[kc][2], qb[kc][3], kb0, kb1);
                MMA_BF16(s[nt], qb[kc][0], qb[kc][1], qb[kc][2], qb[kc][3], ks0, ks1);
                MMA_BF16(s[nt], qs[kc][0], qs[kc][1], qs[kc][2], qs[kc][3], kb0, kb1);
            }
        }
        // Register softmax: rows g (c0,c1) and g+8 (c2,c3); reduce across t-group (xor 1,2)
        float mlo = fmaxf(s[0][0], s[0][1]), mhi = fmaxf(s[0][2], s[0][3]);
        #pragma unroll
        for (int nt = 1; nt < 8; ++nt) {
            mlo = fmaxf(mlo, fmaxf(s[nt][0], s[nt][1]));
            mhi = fmaxf(mhi, fmaxf(s[nt][2], s[nt][3]));
        }
        mlo = fmaxf(mlo, __shfl_xor_sync(0xffffffffu, mlo, 1));
        mlo = fmaxf(mlo, __shfl_xor_sync(0xffffffffu, mlo, 2));
        mhi = fmaxf(mhi, __shfl_xor_sync(0xffffffffu, mhi, 1));
        mhi = fmaxf(mhi, __shfl_xor_sync(0xffffffffu, mhi, 2));
        float llo = 0.f, lhi = 0.f;
        #pragma unroll
        for (int nt = 0; nt < 8; ++nt) {
            s[nt][0] = __expf(s[nt][0] - mlo); s[nt][1] = __expf(s[nt][1] - mlo);
            s[nt][2] = __expf(s[nt][2] - mhi); s[nt][3] = __expf(s[nt][3] - mhi);
            llo += s[nt][0] + s[nt][1];
            lhi += s[nt][2] + s[nt][3];
        }
        llo += __shfl_xor_sync(0xffffffffu, llo, 1);
        llo += __shfl_xor_sync(0xffffffffu, llo, 2);
        lhi += __shfl_xor_sync(0xffffffffu, lhi, 1);
        lhi += __shfl_xor_sync(0xffffffffu, lhi, 2);

        // Re-pack S C-fragments into P A-fragments (registers only, 2-split)
        uint32_t pb[4][4], ps[4][4];
        #pragma unroll
        for (int kc = 0; kc < 4; ++kc) {
            split2(s[2 * kc][0],     s[2 * kc][1],     pb[kc][0], ps[kc][0]);
            split2(s[2 * kc][2],     s[2 * kc][3],     pb[kc][1], ps[kc][1]);
            split2(s[2 * kc + 1][0], s[2 * kc + 1][1], pb[kc][2], ps[kc][2]);
            split2(s[2 * kc + 1][2], s[2 * kc + 1][3], pb[kc][3], ps[kc][3]);
        }
        // O = P V (3-split), V^T B-fragments
        float o[4][4];
        #pragma unroll
        for (int nt2 = 0; nt2 < 4; ++nt2)
            #pragma unroll
            for (int i = 0; i < 4; ++i) o[nt2][i] = 0.f;
        #pragma unroll
        for (int nt2 = 0; nt2 < 4; ++nt2) {
            int dr = (h * 32 + nt2 * 8 + g) * VPAD;
            #pragma unroll
            for (int kc = 0; kc < 4; ++kc) {
                int w0 = dr + kc * 8 + t;
                uint32_t vb0 = VTB[w0], vb1 = VTB[w0 + 4];
                uint32_t vs0 = VTS[w0], vs1 = VTS[w0 + 4];
                MMA_BF16(o[nt2], pb[kc][0], pb[kc][1], pb[kc][2], pb[kc][3], vb0, vb1);
                MMA_BF16(o[nt2], pb[kc][0], pb[kc][1], pb[kc][2], pb[kc][3], vs0, vs1);
                MMA_BF16(o[nt2], ps[kc][0], ps[kc][1], ps[kc][2], ps[kc][3], vb0, vb1);
            }
        }
        // Write O (row-normalized) as packed big/small into AB/AS
        float lilo = 1.f / llo, lihi = 1.f / lhi;
        #pragma unroll
        for (int nt2 = 0; nt2 < 4; ++nt2) {
            int w = r0 * APAD + h * 16 + nt2 * 4 + t;
            uint32_t bb, ss;
            split2(o[nt2][0] * lilo, o[nt2][1] * lilo, bb, ss);
            AB[w] = bb; AS[w] = ss;
            split2(o[nt2][2] * lihi, o[nt2][3] * lihi, bb, ss);
            AB[w + 8 * APAD] = bb; AS[w + 8 * APAD] = ss;
        }
    }
    __syncthreads();

    // ================= Phase 3: proj GEMM (3x bf16 mma), A = O fragments direct ========
    {
        float c[2][3][4];
        #pragma unroll
        for (int mt = 0; mt < 2; ++mt)
            #pragma unroll
            for (int nt = 0; nt < 3; ++nt)
                #pragma unroll
                for (int i = 0; i < 4; ++i) c[mt][nt][i] = 0.f;

        for (int ksg = 0; ksg < 12; ++ksg) {
            uint32_t ab[2][4], as[2][4];
            const int wb = ksg * 8 + t;
            #pragma unroll
            for (int mt = 0; mt < 2; ++mt) {
                int r0 = (mh * 32 + mt * 16 + g) * APAD, r1 = r0 + 8 * APAD;
                ab[mt][0] = AB[r0 + wb];     ab[mt][1] = AB[r1 + wb];
                ab[mt][2] = AB[r0 + wb + 4]; ab[mt][3] = AB[r1 + wb + 4];
                as[mt][0] = AS[r0 + wb];     as[mt][1] = AS[r1 + wb];
                as[mt][2] = AS[r0 + wb + 4]; as[mt][3] = AS[r1 + wb + 4];
            }
            #pragma unroll
            for (int nt = 0; nt < 3; ++nt) {
                uint4 B4 = g_wproj[(ksg * 24 + wc * 3 + nt) * 32 + lane];
                #pragma unroll
                for (int mt = 0; mt < 2; ++mt) {
                    MMA_BF16(c[mt][nt], ab[mt][0], ab[mt][1], ab[mt][2], ab[mt][3], B4.x, B4.y);
                    MMA_BF16(c[mt][nt], ab[mt][0], ab[mt][1], ab[mt][2], ab[mt][3], B4.z, B4.w);
                    MMA_BF16(c[mt][nt], as[mt][0], as[mt][1], as[mt][2], as[mt][3], B4.x, B4.y);
                }
            }
        }
        // Epilogue: + bias, write to gmem
        #pragma unroll
        for (int nt = 0; nt < 3; ++nt) {
            int colbase = wc * 24 + nt * 8 + 2 * t;
            float b0 = proj_b[colbase], b1 = proj_b[colbase + 1];
            #pragma unroll
            for (int mt = 0; mt < 2; ++mt)
                #pragma unroll
                for (int rr = 0; rr < 2; ++rr) {
                    int row = mh * 32 + mt * 16 + g + 8 * rr;
                    float2 v;
                    v.x = c[mt][nt][rr * 2 + 0] + b0;
                    v.y = c[mt][nt][rr * 2 + 1] + b1;
                    *reinterpret_cast<float2*>(ob + row * DIM + colbase) = v;
                }
        }
    }
}

extern "C" void kernel_launch(void* const* d_in, const int* in_sizes, int n_in,
                              void* d_out, int out_size) {
    const float* x          = (const float*)d_in[0];
    const float* qkv_w      = (const float*)d_in[1];
    const float* qkv_b      = (const float*)d_in[2];
    const float* proj_w     = (const float*)d_in[3];
    const float* proj_b     = (const float*)d_in[4];
    const float* bias_table = (const float*)d_in[5];
    const int*   rel_index  = (const int*)d_in[6];
    float* out = (float*)d_out;

    cudaFuncSetAttribute(msa_fused_kernel, cudaFuncAttributeMaxDynamicSharedMemorySize,
                         SMEM_WORDS * (int)sizeof(uint32_t));

    int prep_n = NQ_FRAG + NP_FRAG + NBF;
    prep_kernel<<<(prep_n + 255) / 256, 256>>>(qkv_w, proj_w, bias_table, rel_index);
    msa_fused_kernel<<<NWIN, NTHREADS, SMEM_WORDS * sizeof(uint32_t)>>>(x, qkv_b, proj_b, out);
}